// round 2
// baseline (speedup 1.0000x reference)
#include <cuda_runtime.h>

#define NB 4
#define C  128
#define Q  4096   // HS*WS = HR*WR
#define S  64
#define WS_ 64
#define HS_ 64

// Scratch: transposed features, (n, q, c) layout, 8 MB each.
__device__ float g_fr_t[(size_t)NB * Q * C];
__device__ float g_fs_t[(size_t)NB * Q * C];

// Transpose (n, C, Q) -> (n, Q, C) for both fr and fs.
// grid (Q/32, C/32, 2*NB), block (32, 8)
__global__ void transpose_cq(const float* __restrict__ fr,
                             const float* __restrict__ fs) {
    __shared__ float tile[32][33];
    const int which = blockIdx.z >> 2;      // 0 = fr, 1 = fs
    const int n     = blockIdx.z & 3;
    const float* src = which ? fs : fr;
    float* dst       = which ? g_fs_t : g_fr_t;

    const int q0 = blockIdx.x * 32;
    const int c0 = blockIdx.y * 32;

    const float* sp = src + ((size_t)n * C + c0) * Q + q0;
#pragma unroll
    for (int k = 0; k < 4; ++k)
        tile[threadIdx.y + k * 8][threadIdx.x] =
            sp[(size_t)(threadIdx.y + k * 8) * Q + threadIdx.x];
    __syncthreads();

    float* dp = dst + ((size_t)n * Q + q0) * C + c0;
#pragma unroll
    for (int k = 0; k < 4; ++k)
        dp[(size_t)(threadIdx.y + k * 8) * C + threadIdx.x] =
            tile[threadIdx.x][threadIdx.y + k * 8];
}

// One warp per (n, p). All 64 grid/mask scalars prefetched into lane
// registers up-front; s-loop unrolled x4 so 16 independent float4
// gathers are in flight per warp.
// grid (Q/8, NB), block 256 (8 warps)
__global__ __launch_bounds__(256, 2)
void corr_sample_kernel(const float* __restrict__ grids,
                        const float* __restrict__ mask,
                        float* __restrict__ out) {
    const int lane = threadIdx.x & 31;
    const int warp = threadIdx.x >> 5;
    const int n    = blockIdx.y;
    const int p    = blockIdx.x * 8 + warp;

    // fr_p slice: 4 floats per lane
    const float4 fr4 = *(const float4*)(g_fr_t + ((size_t)n * Q + p) * C + lane * 4);
    const float* fsb = g_fs_t + (size_t)n * Q * C;

    const float* gbase = grids + (size_t)n * S * 2 * Q + p;  // + s*2Q (gx), + Q (gy)
    const float* mbase = mask  + (size_t)n * S * Q + p;      // + s*Q

    // Prefetch: lane holds s=lane and s=lane+32 (all 6 loads independent).
    const float gx_lo = __ldg(gbase + (size_t)lane * 2 * Q);
    const float gx_hi = __ldg(gbase + (size_t)(lane + 32) * 2 * Q);
    const float gy_lo = __ldg(gbase + (size_t)lane * 2 * Q + Q);
    const float gy_hi = __ldg(gbase + (size_t)(lane + 32) * 2 * Q + Q);
    const float mv_lo = __ldg(mbase + (size_t)lane * Q);
    const float mv_hi = __ldg(mbase + (size_t)(lane + 32) * Q);

    __shared__ float s_out[S][8];
    __shared__ float s_cm[S][8];

    for (int s4 = 0; s4 < S; s4 += 4) {
        const bool hi = s4 >= 32;
        const float gxr = hi ? gx_hi : gx_lo;
        const float gyr = hi ? gy_hi : gy_lo;
        const float mvr = hi ? mv_hi : mv_lo;

        float dacc[4], cmv[4], mvv[4];

        // Stage 1: compute all 16 corner addresses + weights, issue all loads.
        float4 f[4][4];
        float  w[4][4];
        float  msum[4];
        float4 frq[4];  // kept per-sample blend accumulators
#pragma unroll
        for (int j = 0; j < 4; ++j) {
            const int s  = s4 + j;
            const float gx = __shfl_sync(0xFFFFFFFFu, gxr, s & 31);
            const float gy = __shfl_sync(0xFFFFFFFFu, gyr, s & 31);
            mvv[j] = __shfl_sync(0xFFFFFFFFu, mvr, s & 31);

            const float ix = gx - 0.5f;
            const float iy = gy - 0.5f;
            const float x0 = floorf(ix);
            const float y0 = floorf(iy);
            const float wx1 = ix - x0;
            const float wy1 = iy - y0;
            const int x0i = (int)x0;
            const int y0i = (int)y0;

            msum[j] = 0.0f;
#pragma unroll
            for (int k = 0; k < 4; ++k) {
                const int dx = k & 1;
                const int dy = k >> 1;
                const int xi = x0i + dx;
                const int yi = y0i + dy;
                const bool inb = (xi >= 0) && (xi < WS_) && (yi >= 0) && (yi < HS_);
                const float wk = (dx ? wx1 : 1.0f - wx1) *
                                 (dy ? wy1 : 1.0f - wy1) * (inb ? 1.0f : 0.0f);
                w[j][k] = wk;
                msum[j] += wk;
                const int xc = min(max(xi, 0), WS_ - 1);
                const int yc = min(max(yi, 0), HS_ - 1);
                const int q  = yc * WS_ + xc;
                f[j][k] = __ldg((const float4*)(fsb + (size_t)q * C + lane * 4));
            }
        }

        // Stage 2: blend + dot + reduce (4 independent trees interleave).
#pragma unroll
        for (int j = 0; j < 4; ++j) {
            float4 v = make_float4(0.f, 0.f, 0.f, 0.f);
#pragma unroll
            for (int k = 0; k < 4; ++k) {
                v.x += w[j][k] * f[j][k].x;
                v.y += w[j][k] * f[j][k].y;
                v.z += w[j][k] * f[j][k].z;
                v.w += w[j][k] * f[j][k].w;
            }
            frq[j] = v;
            dacc[j] = fr4.x * v.x + fr4.y * v.y + fr4.z * v.z + fr4.w * v.w;
            cmv[j]  = (msum[j] < 0.9999f) ? 0.0f : 1.0f;
        }
#pragma unroll
        for (int o = 16; o; o >>= 1) {
#pragma unroll
            for (int j = 0; j < 4; ++j)
                dacc[j] += __shfl_xor_sync(0xFFFFFFFFu, dacc[j], o);
        }
        if (lane == 0) {
#pragma unroll
            for (int j = 0; j < 4; ++j) {
                s_out[s4 + j][warp] = dacc[j] * cmv[j] * mvv[j];
                s_cm[s4 + j][warp]  = cmv[j] * mvv[j];
            }
        }
        (void)frq;
    }

    __syncthreads();

    // Coalesced-ish writeback: out (n,s,p) then corr_mask (n,s,p)
    float* outp = out + (size_t)n * S * Q + blockIdx.x * 8;
    float* cmp  = outp + (size_t)NB * S * Q;
    for (int t = threadIdx.x; t < S * 8; t += 256) {
        const int s = t >> 3;
        const int j = t & 7;
        outp[(size_t)s * Q + j] = s_out[s][j];
        cmp[(size_t)s * Q + j]  = s_cm[s][j];
    }
}

extern "C" void kernel_launch(void* const* d_in, const int* in_sizes, int n_in,
                              void* d_out, int out_size) {
    const float* fr    = (const float*)d_in[0];
    const float* fs    = (const float*)d_in[1];
    const float* grids = (const float*)d_in[2];
    const float* mask  = (const float*)d_in[3];
    float* out = (float*)d_out;

    transpose_cq<<<dim3(Q / 32, C / 32, 2 * NB), dim3(32, 8)>>>(fr, fs);
    corr_sample_kernel<<<dim3(Q / 8, NB), 256>>>(grids, mask, out);
}